// round 4
// baseline (speedup 1.0000x reference)
#include <cuda_runtime.h>
#include <cuda_bf16.h>
#include <cstdint>

// ---------------- problem constants ----------------
#define SEQ    512
#define BATCH  64
#define IN_W   256
#define SW     1024
#define OUT_W  256

// ---------------- kernel config --------------------
#define P_CTAS   64      // persistent CTAs; each owns JS output columns
#define NTHREADS 256     // 8 warps = 4 m-tiles x 2 k-splits
#define JS       16      // output columns per CTA
#define PADC     1032    // padded weight row stride (elems) -> conflict-free LDS

#define LIN_F 0.99999f
__device__ __constant__ float EPS_F = (float)(1.0 - 0.99999);

// ---------------- global scratch ----------------
__device__ float          d_Sf[2][BATCH * SW];   // fp32 state (ping-pong)
__device__ __nv_bfloat16  d_Sh[2][BATCH * SW];   // bf16 shadow of state
__device__ __nv_bfloat16  d_H[BATCH * SW];       // hidden activations (bf16)
__device__ int            d_inv[SW];             // inverse permutation
__device__ unsigned       d_count;               // grid barrier counter

// ---------------- grid barrier: pure spin, release/acquire ----------------
__device__ __forceinline__ void gbar(unsigned& barcnt) {
    __syncthreads();
    if (threadIdx.x == 0) {
        asm volatile("red.release.gpu.global.add.u32 [%0], 1;" :: "l"(&d_count) : "memory");
        unsigned target = (barcnt + 1u) * (unsigned)P_CTAS;
        unsigned v;
        do {
            asm volatile("ld.acquire.gpu.u32 %0, [%1];" : "=r"(v) : "l"(&d_count) : "memory");
        } while (v < target);
    }
    barcnt++;
    __syncthreads();
}

static __device__ __forceinline__ uint32_t ldcg_u32(const uint32_t* p) {
    uint32_t v;
    asm volatile("ld.global.cg.u32 %0, [%1];" : "=r"(v) : "l"(p));
    return v;
}

// mma.sync m16n8k16 bf16 (accumulate fp32)
static __device__ __forceinline__ void mma16816(float& c0, float& c1, float& c2, float& c3,
                                                uint32_t a0, uint32_t a1, uint32_t a2, uint32_t a3,
                                                uint32_t b0, uint32_t b1) {
    asm("mma.sync.aligned.m16n8k16.row.col.f32.bf16.bf16.f32 "
        "{%0,%1,%2,%3}, {%4,%5,%6,%7}, {%8,%9}, {%0,%1,%2,%3};\n"
        : "+f"(c0), "+f"(c1), "+f"(c2), "+f"(c3)
        : "r"(a0), "r"(a1), "r"(a2), "r"(a3), "r"(b0), "r"(b1));
}

// one phase GEMM: acc[8] = act[64x1024] @ Wslice[16x1024]^T, k-split over ks
// A loaded straight from global (L2) via ldcg; B from resident padded smem.
static __device__ __forceinline__ void gemm_ksplit(const __nv_bfloat16* __restrict__ actg,
                                                   const __nv_bfloat16* __restrict__ Ws,
                                                   int r0, int r1, int g, int quad, int ks,
                                                   float* acc) {
#pragma unroll
    for (int u = 0; u < 8; u++) acc[u] = 0.f;

    const uint32_t* pA0 = reinterpret_cast<const uint32_t*>(actg + r0 * SW) + ks * 256 + quad;
    const uint32_t* pA1 = reinterpret_cast<const uint32_t*>(actg + r1 * SW) + ks * 256 + quad;
    const uint32_t* pB0 = reinterpret_cast<const uint32_t*>(Ws + (g)     * PADC) + ks * 256 + quad;
    const uint32_t* pB1 = reinterpret_cast<const uint32_t*>(Ws + (8 + g) * PADC) + ks * 256 + quad;

#pragma unroll
    for (int i = 0; i < 32; i++) {          // 32 k-steps of 16
        uint32_t a0 = ldcg_u32(pA0 + i * 8);
        uint32_t a2 = ldcg_u32(pA0 + i * 8 + 4);
        uint32_t a1 = ldcg_u32(pA1 + i * 8);
        uint32_t a3 = ldcg_u32(pA1 + i * 8 + 4);
        uint32_t b00 = pB0[i * 8], b01 = pB0[i * 8 + 4];
        uint32_t b10 = pB1[i * 8], b11 = pB1[i * 8 + 4];
        mma16816(acc[0], acc[1], acc[2], acc[3], a0, a1, a2, a3, b00, b01);
        mma16816(acc[4], acc[5], acc[6], acc[7], a0, a1, a2, a3, b10, b11);
    }
}

// cross-warp k-reduction through smem: ks=1 stores, ks=0 adds. One syncthreads.
static __device__ __forceinline__ void kreduce(float* Red, int mt, int lane, int ks, float* acc) {
    int base = mt * 32 + lane;
    if (ks == 1) {
#pragma unroll
        for (int u = 0; u < 8; u++) Red[u * 128 + base] = acc[u];
    }
    __syncthreads();
    if (ks == 0) {
#pragma unroll
        for (int u = 0; u < 8; u++) acc[u] += Red[u * 128 + base];
    }
}

// ---------------- setup: inverse perm, S0, barrier reset ----------------
__global__ void setup_kernel(const float* __restrict__ x,
                             const float* __restrict__ init,
                             const int* __restrict__ rp) {
    int tid = blockIdx.x * blockDim.x + threadIdx.x;
    if (tid == 0) d_count = 0u;
    if (tid < SW) d_inv[rp[tid]] = tid;
    const float eps = EPS_F;
    for (int e = tid; e < BATCH * SW; e += gridDim.x * blockDim.x) {
        int b = e >> 10, p = e & (SW - 1);
        int q = rp[p];
        float v = eps * init[q];
        if (q < IN_W) v += x[b * IN_W + q];   // x[t=0]
        d_Sf[0][b * SW + p] = v;
        d_Sh[0][b * SW + p] = __float2bfloat16(v);
    }
}

// ---------------- persistent RNN kernel ----------------
__global__ void __launch_bounds__(NTHREADS, 1)
resrnn_kernel(const float* __restrict__ x,
              const float* __restrict__ W1, const float* __restrict__ b1,
              const float* __restrict__ W2, const float* __restrict__ b2,
              float* __restrict__ out, int out_size) {
    extern __shared__ __nv_bfloat16 smem[];
    __nv_bfloat16* W1s = smem;                      // [JS][PADC]
    __nv_bfloat16* W2s = smem + JS * PADC;          // [JS][PADC]
    float*         Red = reinterpret_cast<float*>(smem + 2 * JS * PADC);  // [8][128]

    const int tid   = threadIdx.x;
    const int cta   = blockIdx.x;
    const int jbase = cta * JS;

    // ---- load weight slices once (fp32 -> bf16), resident for all 512 steps ----
    for (int e = tid; e < JS * (SW / 4); e += NTHREADS) {
        int n  = e / (SW / 4);
        int k4 = e % (SW / 4);
        float4 v = reinterpret_cast<const float4*>(W1 + (size_t)(jbase + n) * SW)[k4];
        __nv_bfloat16* d1 = W1s + n * PADC + k4 * 4;
        d1[0] = __float2bfloat16(v.x); d1[1] = __float2bfloat16(v.y);
        d1[2] = __float2bfloat16(v.z); d1[3] = __float2bfloat16(v.w);
        float4 w = reinterpret_cast<const float4*>(W2 + (size_t)(jbase + n) * SW)[k4];
        __nv_bfloat16* d2 = W2s + n * PADC + k4 * 4;
        d2[0] = __float2bfloat16(w.x); d2[1] = __float2bfloat16(w.y);
        d2[2] = __float2bfloat16(w.z); d2[3] = __float2bfloat16(w.w);
    }
    __syncthreads();

    // ---- per-thread static coordinates ----
    const int warp = tid >> 5, lane = tid & 31;
    const int mt = warp & 3, ks = warp >> 2;        // 4 m-tiles x 2 k-splits
    const int g  = lane >> 2, quad = lane & 3, tc = quad * 2;
    const int r0 = mt * 16 + g, r1 = r0 + 8;        // batch rows
    // output columns owned by this thread (both n-tiles): j[nt] = jbase + nt*8 + tc (+1)
    const int j00 = jbase + tc,     j01 = j00 + 1;
    const int j10 = jbase + 8 + tc, j11 = j10 + 1;
    const float bb1[4] = { b1[j00], b1[j01], b1[j10], b1[j11] };
    const float bb2[4] = { b2[j00], b2[j01], b2[j10], b2[j11] };
    const int ip[4] = { d_inv[j00], d_inv[j01], d_inv[j10], d_inv[j11] };
    const float eps = EPS_F;
    unsigned barcnt = 0;
    float acc[8];

    for (int t = 0; t < SEQ; t++) {
        const int cur = t & 1, nxt = cur ^ 1;

        // ================= phase 1: h = relu(S @ W1^T + b1) =================
        gemm_ksplit(d_Sh[cur], W1s, r0, r1, g, quad, ks, acc);
        kreduce(Red, mt, lane, ks, acc);
        if (ks == 0) {
            __nv_bfloat162* Hp = reinterpret_cast<__nv_bfloat162*>(d_H);
            float h0 = fmaxf(acc[0] + bb1[0], 0.f), h1 = fmaxf(acc[1] + bb1[1], 0.f);
            float h2 = fmaxf(acc[2] + bb1[0], 0.f), h3 = fmaxf(acc[3] + bb1[1], 0.f);
            float h4 = fmaxf(acc[4] + bb1[2], 0.f), h5 = fmaxf(acc[5] + bb1[3], 0.f);
            float h6 = fmaxf(acc[6] + bb1[2], 0.f), h7 = fmaxf(acc[7] + bb1[3], 0.f);
            Hp[(r0 * SW + j00) >> 1] = __floats2bfloat162_rn(h0, h1);
            Hp[(r1 * SW + j00) >> 1] = __floats2bfloat162_rn(h2, h3);
            Hp[(r0 * SW + j10) >> 1] = __floats2bfloat162_rn(h4, h5);
            Hp[(r1 * SW + j10) >> 1] = __floats2bfloat162_rn(h6, h7);
        }
        gbar(barcnt);

        // ================= phase 2: y = h @ W2^T + b2 ; fused update ========
        gemm_ksplit(d_H, W2s, r0, r1, g, quad, ks, acc);
        kreduce(Red, mt, lane, ks, acc);
        if (ks == 0) {
            // y values: [row r0/r1][col pair] for both n-tiles
            float y[8];
            y[0] = acc[0] + bb2[0]; y[1] = acc[1] + bb2[1];
            y[2] = acc[2] + bb2[0]; y[3] = acc[3] + bb2[1];
            y[4] = acc[4] + bb2[2]; y[5] = acc[5] + bb2[3];
            y[6] = acc[6] + bb2[2]; y[7] = acc[7] + bb2[3];
            const int rr[8] = { r0, r0, r1, r1, r0, r0, r1, r1 };
            const int jj[8] = { j00, j01, j00, j01, j10, j11, j10, j11 };
            const int pp[8] = { ip[0], ip[1], ip[0], ip[1], ip[2], ip[3], ip[2], ip[3] };
            const float* Sc = d_Sf[cur];
            float nv[8];
#pragma unroll
            for (int u = 0; u < 8; u++) {
                float s;
                asm volatile("ld.global.cg.f32 %0, [%1];" : "=f"(s) : "l"(Sc + rr[u] * SW + jj[u]));
                nv[u] = LIN_F * s + eps * y[u];
            }
            if (t < SEQ - 1) {
                if (jbase < IN_W) {   // all 16 of this CTA's columns are input columns
                    const float* xp = x + (size_t)(t + 1) * BATCH * IN_W;
#pragma unroll
                    for (int u = 0; u < 8; u++) nv[u] += xp[rr[u] * IN_W + jj[u]];
                }
                float* Sn = d_Sf[nxt];
                __nv_bfloat16* Shn = d_Sh[nxt];
#pragma unroll
                for (int u = 0; u < 8; u++) {
                    int a = rr[u] * SW + pp[u];
                    Sn[a]  = nv[u];
                    Shn[a] = __float2bfloat16(nv[u]);
                }
            } else {
#pragma unroll
                for (int u = 0; u < 8; u++) {
                    int b = rr[u], i = jj[u];
                    float v = nv[u];
                    if (out_size == BATCH * (OUT_W + SW)) {           // (outputs, last)
                        out[BATCH * OUT_W + b * SW + i] = v;
                        if (i >= SW - OUT_W) out[b * OUT_W + (i - (SW - OUT_W))] = v;
                    } else if (out_size == BATCH * SW) {              // last only
                        out[b * SW + i] = v;
                    } else {                                          // outputs only
                        if (i >= SW - OUT_W) out[b * OUT_W + (i - (SW - OUT_W))] = v;
                    }
                }
            }
        }
        gbar(barcnt);
    }
}

// ---------------- launch ----------------
extern "C" void kernel_launch(void* const* d_in, const int* in_sizes, int n_in,
                              void* d_out, int out_size) {
    const float* x    = (const float*)d_in[0];
    const float* init = (const float*)d_in[1];
    const int*   rp   = (const int*)  d_in[2];
    const float* W1   = (const float*)d_in[3];
    const float* b1   = (const float*)d_in[4];
    const float* W2   = (const float*)d_in[5];
    const float* b2   = (const float*)d_in[6];

    setup_kernel<<<64, 256>>>(x, init, rp);

    const int smem_bytes = 2 * JS * PADC * (int)sizeof(__nv_bfloat16) + 8 * 128 * (int)sizeof(float);
    cudaFuncSetAttribute(resrnn_kernel, cudaFuncAttributeMaxDynamicSharedMemorySize, smem_bytes);
    resrnn_kernel<<<P_CTAS, NTHREADS, smem_bytes>>>(x, W1, b1, W2, b2,
                                                    (float*)d_out, out_size);
}

// round 5
// speedup vs baseline: 1.2471x; 1.2471x over previous
#include <cuda_runtime.h>
#include <cuda_bf16.h>
#include <cstdint>

// ---------------- problem constants ----------------
#define SEQ    512
#define BATCH  64
#define IN_W   256
#define SW     1024
#define OUT_W  256

// ---------------- kernel config --------------------
#define P_CTAS   128     // 2 batch-halves x 64 col-groups
#define NTHREADS 256     // 8 warps = 2 m-tiles x 4 k-splits
#define JS       16      // output columns per CTA
#define ROWS     32      // batch rows per CTA
#define PADC     1032    // padded row stride in elems (2064B = 16 mod 128 -> LDSM conflict-free)

#define LIN_F 0.99999f
__device__ __constant__ float EPS_F = (float)(1.0 - 0.99999);

// ---------------- global scratch ----------------
__device__ float          d_Sf[2][BATCH * SW];   // fp32 state (ping-pong)
__device__ __nv_bfloat16  d_Sh[2][BATCH * SW];   // bf16 shadow of state
__device__ __nv_bfloat16  d_H[BATCH * SW];       // hidden activations (bf16)
__device__ int            d_inv[SW];             // inverse permutation
__device__ unsigned       d_cnt[8 * 64];         // distributed barrier counters (256B apart)

// ---------------- helpers ----------------
static __device__ __forceinline__ unsigned smem_u32(const void* p) {
    return (unsigned)__cvta_generic_to_shared(p);
}

// distributed grid barrier: 8 counters, release/acquire
__device__ __forceinline__ void gbar(unsigned& barcnt, int cta) {
    __syncthreads();
    if (threadIdx.x == 0) {
        unsigned* cnt = d_cnt + (cta & 7) * 64;
        asm volatile("red.release.gpu.global.add.u32 [%0], 1;" :: "l"(cnt) : "memory");
        const unsigned target = (barcnt + 1u) * (unsigned)P_CTAS;
        unsigned total;
        do {
            total = 0;
#pragma unroll
            for (int i = 0; i < 8; i++) {
                unsigned v;
                asm volatile("ld.acquire.gpu.u32 %0, [%1];" : "=r"(v) : "l"(d_cnt + i * 64) : "memory");
                total += v;
            }
        } while (total < target);
    }
    barcnt++;
    __syncthreads();
}

static __device__ __forceinline__ void ldsm4(uint32_t& r0, uint32_t& r1, uint32_t& r2, uint32_t& r3,
                                             unsigned addr) {
    asm volatile("ldmatrix.sync.aligned.m8n8.x4.shared.b16 {%0,%1,%2,%3}, [%4];"
                 : "=r"(r0), "=r"(r1), "=r"(r2), "=r"(r3) : "r"(addr));
}

static __device__ __forceinline__ void mma16816(float* c,
                                                uint32_t a0, uint32_t a1, uint32_t a2, uint32_t a3,
                                                uint32_t b0, uint32_t b1) {
    asm("mma.sync.aligned.m16n8k16.row.col.f32.bf16.bf16.f32 "
        "{%0,%1,%2,%3}, {%4,%5,%6,%7}, {%8,%9}, {%0,%1,%2,%3};\n"
        : "+f"(c[0]), "+f"(c[1]), "+f"(c[2]), "+f"(c[3])
        : "r"(a0), "r"(a1), "r"(a2), "r"(a3), "r"(b0), "r"(b1));
}

// one phase GEMM: copy act[32x1024] (this CTA's batch rows) into padded smem,
// then acc[8] = act @ Wslice[16x1024]^T with 4-way k-split per warp.
static __device__ __forceinline__ void gemm_phase(const __nv_bfloat16* __restrict__ actg,
                                                  __nv_bfloat16* Act, unsigned actU32,
                                                  unsigned wsU32,
                                                  int tid, unsigned aOff, unsigned bOff,
                                                  float* acc) {
    // ---- bulk copy 64KB: 16 x cp.async.cg(16B) per thread, padded dst ----
#pragma unroll
    for (int q = 0; q < 4; q++) {
        int e0 = tid + q * 4 * NTHREADS;    // issue in 4 groups of 4 for code size
#pragma unroll
        for (int s = 0; s < 4; s++) {
            int e = e0 + s * NTHREADS;      // 0..4095
            int row = e >> 7;               // 128 segs of 16B per 2KB row
            int seg = e & 127;
            unsigned dst = smem_u32(Act + row * PADC + seg * 8);
            const void* src = (const void*)(actg + row * SW + seg * 8);
            asm volatile("cp.async.cg.shared.global [%0], [%1], 16;\n" :: "r"(dst), "l"(src));
        }
    }
    asm volatile("cp.async.commit_group;\n" ::: "memory");
    asm volatile("cp.async.wait_group 0;\n" ::: "memory");
    __syncthreads();

    // ---- MMA: 16 k-steps of m16n16k16 ----
#pragma unroll
    for (int u = 0; u < 8; u++) acc[u] = 0.f;
    unsigned aA = actU32 + aOff;
    unsigned aB = wsU32 + bOff;
#pragma unroll
    for (int ki = 0; ki < 16; ki++) {
        uint32_t a0, a1, a2, a3, b0, b1, b2, b3;
        ldsm4(a0, a1, a2, a3, aA + ki * 32);
        ldsm4(b0, b1, b2, b3, aB + ki * 32);
        mma16816(acc,     a0, a1, a2, a3, b0, b2);   // n-tile 0 (cols 0-7)
        mma16816(acc + 4, a0, a1, a2, a3, b1, b3);   // n-tile 1 (cols 8-15)
    }
}

// cross-warp k-reduction (4-way): kq>0 store, kq==0 add. One syncthreads.
static __device__ __forceinline__ void kreduce(float* Red, int m, int kq, int lane, float* acc) {
    if (kq > 0) {
        float* slot = Red + ((kq - 1) * 2 + m) * 256;
#pragma unroll
        for (int u = 0; u < 8; u++) slot[u * 32 + lane] = acc[u];
    }
    __syncthreads();
    if (kq == 0) {
#pragma unroll
        for (int k = 0; k < 3; k++) {
            const float* slot = Red + (k * 2 + m) * 256;
#pragma unroll
            for (int u = 0; u < 8; u++) acc[u] += slot[u * 32 + lane];
        }
    }
}

// ---------------- setup: inverse perm, S0, barrier reset ----------------
__global__ void setup_kernel(const float* __restrict__ x,
                             const float* __restrict__ init,
                             const int* __restrict__ rp) {
    int tid = blockIdx.x * blockDim.x + threadIdx.x;
    if (tid < 8 * 64) d_cnt[tid] = 0u;
    if (tid < SW) d_inv[rp[tid]] = tid;
    const float eps = EPS_F;
    for (int e = tid; e < BATCH * SW; e += gridDim.x * blockDim.x) {
        int b = e >> 10, p = e & (SW - 1);
        int q = rp[p];
        float v = eps * init[q];
        if (q < IN_W) v += x[b * IN_W + q];   // x[t=0]
        d_Sf[0][b * SW + p] = v;
        d_Sh[0][b * SW + p] = __float2bfloat16(v);
    }
}

// ---------------- persistent RNN kernel ----------------
__global__ void __launch_bounds__(NTHREADS, 1)
resrnn_kernel(const float* __restrict__ x,
              const float* __restrict__ W1, const float* __restrict__ b1,
              const float* __restrict__ W2, const float* __restrict__ b2,
              float* __restrict__ out, int out_size) {
    extern __shared__ __nv_bfloat16 smem[];
    __nv_bfloat16* W1s = smem;                       // [JS][PADC]
    __nv_bfloat16* W2s = smem + JS * PADC;           // [JS][PADC]
    __nv_bfloat16* Act = smem + 2 * JS * PADC;       // [ROWS][PADC]
    float*         Red = reinterpret_cast<float*>(smem + 2 * JS * PADC + ROWS * PADC); // [6][256]

    const int tid   = threadIdx.x;
    const int cta   = blockIdx.x;
    const int cg    = cta & 63;          // column group
    const int bh    = cta >> 6;          // batch half
    const int jbase = cg * JS;
    const int rbase = bh * ROWS;         // global batch row base

    // ---- load weight slices once (fp32 -> bf16), resident for all steps ----
    for (int e = tid; e < JS * (SW / 4); e += NTHREADS) {
        int n  = e / (SW / 4);
        int k4 = e % (SW / 4);
        float4 v = reinterpret_cast<const float4*>(W1 + (size_t)(jbase + n) * SW)[k4];
        __nv_bfloat16* d1 = W1s + n * PADC + k4 * 4;
        d1[0] = __float2bfloat16(v.x); d1[1] = __float2bfloat16(v.y);
        d1[2] = __float2bfloat16(v.z); d1[3] = __float2bfloat16(v.w);
        float4 w = reinterpret_cast<const float4*>(W2 + (size_t)(jbase + n) * SW)[k4];
        __nv_bfloat16* d2 = W2s + n * PADC + k4 * 4;
        d2[0] = __float2bfloat16(w.x); d2[1] = __float2bfloat16(w.y);
        d2[2] = __float2bfloat16(w.z); d2[3] = __float2bfloat16(w.w);
    }
    __syncthreads();

    // ---- per-thread static coordinates ----
    const int warp = tid >> 5, lane = tid & 31;
    const int m  = warp & 1;             // m-tile (16 rows)
    const int kq = warp >> 1;            // k-quarter (256 elems)
    const int g  = lane >> 2, quad = lane & 3, tc = quad * 2;

    // ldmatrix source offsets (bytes)
    const unsigned aOff = (unsigned)((m * 16 + (lane & 15)) * (PADC * 2) + ((lane >> 4) << 4) + kq * 512);
    const unsigned bOff = (unsigned)(((lane & 15)) * (PADC * 2) + ((lane >> 4) << 4) + kq * 512);
    const unsigned actU32 = smem_u32(Act);
    const unsigned w1U32  = smem_u32(W1s);
    const unsigned w2U32  = smem_u32(W2s);

    // epilogue coordinates (kq==0 warps): rows within CTA block, global cols
    const int r0 = m * 16 + g, r1 = r0 + 8;              // local rows
    const int gr0 = rbase + r0, gr1 = rbase + r1;        // global rows
    const int j00 = jbase + tc,     j01 = j00 + 1;
    const int j10 = jbase + 8 + tc, j11 = j10 + 1;
    const float bb1[4] = { b1[j00], b1[j01], b1[j10], b1[j11] };
    const float bb2[4] = { b2[j00], b2[j01], b2[j10], b2[j11] };
    const int ip[4] = { d_inv[j00], d_inv[j01], d_inv[j10], d_inv[j11] };
    const float eps = EPS_F;
    unsigned barcnt = 0;
    float acc[8];

    for (int t = 0; t < SEQ; t++) {
        const int cur = t & 1, nxt = cur ^ 1;

        // ================= phase 1: h = relu(S @ W1^T + b1) =================
        gemm_phase(d_Sh[cur] + (size_t)rbase * SW, Act, actU32, w1U32, tid, aOff, bOff, acc);
        kreduce(Red, m, kq, lane, acc);
        if (kq == 0) {
            __nv_bfloat162* Hp = reinterpret_cast<__nv_bfloat162*>(d_H);
            float h0 = fmaxf(acc[0] + bb1[0], 0.f), h1 = fmaxf(acc[1] + bb1[1], 0.f);
            float h2 = fmaxf(acc[2] + bb1[0], 0.f), h3 = fmaxf(acc[3] + bb1[1], 0.f);
            float h4 = fmaxf(acc[4] + bb1[2], 0.f), h5 = fmaxf(acc[5] + bb1[3], 0.f);
            float h6 = fmaxf(acc[6] + bb1[2], 0.f), h7 = fmaxf(acc[7] + bb1[3], 0.f);
            Hp[(gr0 * SW + j00) >> 1] = __floats2bfloat162_rn(h0, h1);
            Hp[(gr1 * SW + j00) >> 1] = __floats2bfloat162_rn(h2, h3);
            Hp[(gr0 * SW + j10) >> 1] = __floats2bfloat162_rn(h4, h5);
            Hp[(gr1 * SW + j10) >> 1] = __floats2bfloat162_rn(h6, h7);
        }
        gbar(barcnt, cta);

        // ================= phase 2: y = h @ W2^T + b2 ; fused update ========
        gemm_phase(d_H + (size_t)rbase * SW, Act, actU32, w2U32, tid, aOff, bOff, acc);
        kreduce(Red, m, kq, lane, acc);
        if (kq == 0) {
            float y[8];
            y[0] = acc[0] + bb2[0]; y[1] = acc[1] + bb2[1];
            y[2] = acc[2] + bb2[0]; y[3] = acc[3] + bb2[1];
            y[4] = acc[4] + bb2[2]; y[5] = acc[5] + bb2[3];
            y[6] = acc[6] + bb2[2]; y[7] = acc[7] + bb2[3];
            const int rr[8] = { gr0, gr0, gr1, gr1, gr0, gr0, gr1, gr1 };
            const int jj[8] = { j00, j01, j00, j01, j10, j11, j10, j11 };
            const int pp[8] = { ip[0], ip[1], ip[0], ip[1], ip[2], ip[3], ip[2], ip[3] };
            const float* Sc = d_Sf[cur];
            float nv[8];
#pragma unroll
            for (int u = 0; u < 8; u++) {
                float s;
                asm volatile("ld.global.cg.f32 %0, [%1];" : "=f"(s) : "l"(Sc + rr[u] * SW + jj[u]));
                nv[u] = LIN_F * s + eps * y[u];
            }
            if (t < SEQ - 1) {
                if (jbase < IN_W) {  // all 16 of this CTA's columns are input columns
                    const float* xp = x + (size_t)(t + 1) * BATCH * IN_W;
#pragma unroll
                    for (int u = 0; u < 8; u++) nv[u] += xp[rr[u] * IN_W + jj[u]];
                }
                float* Sn = d_Sf[nxt];
                __nv_bfloat16* Shn = d_Sh[nxt];
#pragma unroll
                for (int u = 0; u < 8; u++) {
                    int a = rr[u] * SW + pp[u];
                    Sn[a]  = nv[u];
                    Shn[a] = __float2bfloat16(nv[u]);
                }
            } else {
#pragma unroll
                for (int u = 0; u < 8; u++) {
                    int b = rr[u], i = jj[u];
                    float v = nv[u];
                    if (out_size == BATCH * (OUT_W + SW)) {           // (outputs, last)
                        out[BATCH * OUT_W + b * SW + i] = v;
                        if (i >= SW - OUT_W) out[b * OUT_W + (i - (SW - OUT_W))] = v;
                    } else if (out_size == BATCH * SW) {              // last only
                        out[b * SW + i] = v;
                    } else {                                          // outputs only
                        if (i >= SW - OUT_W) out[b * OUT_W + (i - (SW - OUT_W))] = v;
                    }
                }
            }
        }
        gbar(barcnt, cta);
    }
}

// ---------------- launch ----------------
extern "C" void kernel_launch(void* const* d_in, const int* in_sizes, int n_in,
                              void* d_out, int out_size) {
    const float* x    = (const float*)d_in[0];
    const float* init = (const float*)d_in[1];
    const int*   rp   = (const int*)  d_in[2];
    const float* W1   = (const float*)d_in[3];
    const float* b1   = (const float*)d_in[4];
    const float* W2   = (const float*)d_in[5];
    const float* b2   = (const float*)d_in[6];

    setup_kernel<<<64, 256>>>(x, init, rp);

    const int smem_bytes = (2 * JS * PADC + ROWS * PADC) * (int)sizeof(__nv_bfloat16)
                         + 6 * 256 * (int)sizeof(float);
    cudaFuncSetAttribute(resrnn_kernel, cudaFuncAttributeMaxDynamicSharedMemorySize, smem_bytes);
    resrnn_kernel<<<P_CTAS, NTHREADS, smem_bytes>>>(x, W1, b1, W2, b2,
                                                    (float*)d_out, out_size);
}

// round 6
// speedup vs baseline: 1.2826x; 1.0285x over previous
#include <cuda_runtime.h>
#include <cuda_bf16.h>
#include <cstdint>

// ---------------- problem constants ----------------
#define SEQ    512
#define BATCH  64
#define IN_W   256
#define SW     1024
#define OUT_W  256

// ---------------- kernel config --------------------
#define P_CTAS   128     // 2 independent batch-halves x 64 col-groups
#define HALF_CTAS 64
#define NTHREADS 256     // 8 warps = 2 m-tiles x 4 k-splits
#define JS       16      // output columns per CTA
#define ROWS     32      // batch rows per CTA
#define PADC     1032    // padded row stride in elems (2064B = 16 mod 128 -> LDSM conflict-free)

#define LIN_F 0.99999f
__device__ __constant__ float EPS_F = (float)(1.0 - 0.99999);

// ---------------- global scratch ----------------
__device__ float          d_Sf[2][BATCH * SW];   // fp32 state (ping-pong)
__device__ __nv_bfloat16  d_Sh[2][BATCH * SW];   // bf16 shadow of state
__device__ __nv_bfloat16  d_H[BATCH * SW];       // hidden activations (bf16)
__device__ int            d_inv[SW];             // inverse permutation
__device__ unsigned       d_cnt[16 * 64];        // per-half distributed barrier counters

// ---------------- helpers ----------------
static __device__ __forceinline__ unsigned smem_u32(const void* p) {
    return (unsigned)__cvta_generic_to_shared(p);
}

// batch-half-scoped grid barrier: 8 counters per half, 8 arrivals each
__device__ __forceinline__ void gbar(unsigned& barcnt, int bh, int cg) {
    __syncthreads();
    if (threadIdx.x == 0) {
        unsigned* base = d_cnt + bh * 8 * 64;
        unsigned* cnt  = base + (cg & 7) * 64;
        asm volatile("red.release.gpu.global.add.u32 [%0], 1;" :: "l"(cnt) : "memory");
        const unsigned target = (barcnt + 1u) * (unsigned)HALF_CTAS;
        unsigned total;
        do {
            total = 0;
#pragma unroll
            for (int i = 0; i < 8; i++) {
                unsigned v;
                asm volatile("ld.acquire.gpu.u32 %0, [%1];" : "=r"(v) : "l"(base + i * 64) : "memory");
                total += v;
            }
        } while (total < target);
    }
    barcnt++;
    __syncthreads();
}

static __device__ __forceinline__ void ldsm4(uint32_t& r0, uint32_t& r1, uint32_t& r2, uint32_t& r3,
                                             unsigned addr) {
    asm volatile("ldmatrix.sync.aligned.m8n8.x4.shared.b16 {%0,%1,%2,%3}, [%4];"
                 : "=r"(r0), "=r"(r1), "=r"(r2), "=r"(r3) : "r"(addr));
}

static __device__ __forceinline__ void mma16816(float* c,
                                                uint32_t a0, uint32_t a1, uint32_t a2, uint32_t a3,
                                                uint32_t b0, uint32_t b1) {
    asm("mma.sync.aligned.m16n8k16.row.col.f32.bf16.bf16.f32 "
        "{%0,%1,%2,%3}, {%4,%5,%6,%7}, {%8,%9}, {%0,%1,%2,%3};\n"
        : "+f"(c[0]), "+f"(c[1]), "+f"(c[2]), "+f"(c[3])
        : "r"(a0), "r"(a1), "r"(a2), "r"(a3), "r"(b0), "r"(b1));
}

static __device__ __forceinline__ void ld2cg(float& a, float& b, const float* p) {
    asm volatile("ld.global.cg.v2.f32 {%0,%1}, [%2];" : "=f"(a), "=f"(b) : "l"(p));
}

// MMA over this warp's k-quarter with dual accumulators (chain depth 8)
static __device__ __forceinline__ void mma_quarter(unsigned aA, unsigned aB, float* acc) {
    float accB[8];
#pragma unroll
    for (int u = 0; u < 8; u++) { acc[u] = 0.f; accB[u] = 0.f; }
#pragma unroll
    for (int ki = 0; ki < 16; ki += 2) {
        uint32_t a0, a1, a2, a3, b0, b1, b2, b3;
        ldsm4(a0, a1, a2, a3, aA + ki * 32);
        ldsm4(b0, b1, b2, b3, aB + ki * 32);
        mma16816(acc,     a0, a1, a2, a3, b0, b2);
        mma16816(acc + 4, a0, a1, a2, a3, b1, b3);
        ldsm4(a0, a1, a2, a3, aA + (ki + 1) * 32);
        ldsm4(b0, b1, b2, b3, aB + (ki + 1) * 32);
        mma16816(accB,     a0, a1, a2, a3, b0, b2);
        mma16816(accB + 4, a0, a1, a2, a3, b1, b3);
    }
#pragma unroll
    for (int u = 0; u < 8; u++) acc[u] += accB[u];
}

// one phase GEMM: pipelined copy (two 16-row chunks) + k-split MMA
static __device__ __forceinline__ void gemm_phase(const __nv_bfloat16* __restrict__ actg,
                                                  __nv_bfloat16* Act, unsigned actU32,
                                                  unsigned wsU32,
                                                  int tid, int m, unsigned aOff, unsigned bOff,
                                                  float* acc) {
    // chunk 0: rows 0-15 (2048 x 16B), chunk 1: rows 16-31
#pragma unroll
    for (int c = 0; c < 2; c++) {
#pragma unroll
        for (int s = 0; s < 8; s++) {
            int e = tid + s * NTHREADS;          // 0..2047
            int row = c * 16 + (e >> 7);
            int seg = e & 127;
            unsigned dst = smem_u32(Act + row * PADC + seg * 8);
            const void* src = (const void*)(actg + row * SW + seg * 8);
            asm volatile("cp.async.cg.shared.global [%0], [%1], 16;\n" :: "r"(dst), "l"(src));
        }
        asm volatile("cp.async.commit_group;\n" ::: "memory");
    }
    unsigned aA = actU32 + aOff;
    unsigned aB = wsU32 + bOff;
    asm volatile("cp.async.wait_group 1;\n" ::: "memory");
    __syncthreads();                              // rows 0-15 visible
    if (m == 0) mma_quarter(aA, aB, acc);
    asm volatile("cp.async.wait_group 0;\n" ::: "memory");
    __syncthreads();                              // rows 16-31 visible
    if (m == 1) mma_quarter(aA, aB, acc);
}

// cross-warp k-reduction (4-way): kq>0 store, kq==0 add. One syncthreads.
static __device__ __forceinline__ void kreduce(float* Red, int m, int kq, int lane, float* acc) {
    if (kq > 0) {
        float* slot = Red + ((kq - 1) * 2 + m) * 256;
#pragma unroll
        for (int u = 0; u < 8; u++) slot[u * 32 + lane] = acc[u];
    }
    __syncthreads();
    if (kq == 0) {
#pragma unroll
        for (int k = 0; k < 3; k++) {
            const float* slot = Red + (k * 2 + m) * 256;
#pragma unroll
            for (int u = 0; u < 8; u++) acc[u] += slot[u * 32 + lane];
        }
    }
}

// ---------------- setup: inverse perm, S0, barrier reset ----------------
__global__ void setup_kernel(const float* __restrict__ x,
                             const float* __restrict__ init,
                             const int* __restrict__ rp) {
    int tid = blockIdx.x * blockDim.x + threadIdx.x;
    if (tid < 16 * 64) d_cnt[tid] = 0u;
    if (tid < SW) d_inv[rp[tid]] = tid;
    const float eps = EPS_F;
    for (int e = tid; e < BATCH * SW; e += gridDim.x * blockDim.x) {
        int b = e >> 10, p = e & (SW - 1);
        int q = rp[p];
        float v = eps * init[q];
        if (q < IN_W) v += x[b * IN_W + q];   // x[t=0]
        d_Sf[0][b * SW + p] = v;
        d_Sh[0][b * SW + p] = __float2bfloat16(v);
    }
}

// ---------------- persistent RNN kernel ----------------
__global__ void __launch_bounds__(NTHREADS, 1)
resrnn_kernel(const float* __restrict__ x,
              const float* __restrict__ W1, const float* __restrict__ b1,
              const float* __restrict__ W2, const float* __restrict__ b2,
              float* __restrict__ out, int out_size) {
    extern __shared__ __nv_bfloat16 smem[];
    __nv_bfloat16* W1s = smem;                       // [JS][PADC]
    __nv_bfloat16* W2s = smem + JS * PADC;           // [JS][PADC]
    __nv_bfloat16* Act = smem + 2 * JS * PADC;       // [ROWS][PADC]
    float*         Red = reinterpret_cast<float*>(smem + 2 * JS * PADC + ROWS * PADC); // [6][256]

    const int tid   = threadIdx.x;
    const int cta   = blockIdx.x;
    const int cg    = cta & 63;          // column group
    const int bh    = cta >> 6;          // batch half (independent recurrence!)
    const int jbase = cg * JS;
    const int rbase = bh * ROWS;         // global batch row base

    // ---- load weight slices once (fp32 -> bf16), resident for all steps ----
    for (int e = tid; e < JS * (SW / 4); e += NTHREADS) {
        int n  = e / (SW / 4);
        int k4 = e % (SW / 4);
        float4 v = reinterpret_cast<const float4*>(W1 + (size_t)(jbase + n) * SW)[k4];
        __nv_bfloat16* d1 = W1s + n * PADC + k4 * 4;
        d1[0] = __float2bfloat16(v.x); d1[1] = __float2bfloat16(v.y);
        d1[2] = __float2bfloat16(v.z); d1[3] = __float2bfloat16(v.w);
        float4 w = reinterpret_cast<const float4*>(W2 + (size_t)(jbase + n) * SW)[k4];
        __nv_bfloat16* d2 = W2s + n * PADC + k4 * 4;
        d2[0] = __float2bfloat16(w.x); d2[1] = __float2bfloat16(w.y);
        d2[2] = __float2bfloat16(w.z); d2[3] = __float2bfloat16(w.w);
    }
    __syncthreads();

    // ---- per-thread static coordinates ----
    const int warp = tid >> 5, lane = tid & 31;
    const int m  = warp & 1;             // m-tile (16 rows)
    const int kq = warp >> 1;            // k-quarter (256 elems)
    const int g  = lane >> 2, quad = lane & 3, tc = quad * 2;

    // ldmatrix source offsets (bytes)
    const unsigned aOff = (unsigned)((m * 16 + (lane & 15)) * (PADC * 2) + ((lane >> 4) << 4) + kq * 512);
    const unsigned bOff = (unsigned)(((lane & 15)) * (PADC * 2) + ((lane >> 4) << 4) + kq * 512);
    const unsigned actU32 = smem_u32(Act);
    const unsigned w1U32  = smem_u32(W1s);
    const unsigned w2U32  = smem_u32(W2s);

    // epilogue coordinates (kq==0 warps)
    const int r0 = m * 16 + g, r1 = r0 + 8;
    const int gr0 = rbase + r0, gr1 = rbase + r1;
    const int j00 = jbase + tc,     j01 = j00 + 1;
    const int j10 = jbase + 8 + tc, j11 = j10 + 1;
    const float bb1[4] = { b1[j00], b1[j01], b1[j10], b1[j11] };
    const float bb2[4] = { b2[j00], b2[j01], b2[j10], b2[j11] };
    const int ip[4] = { d_inv[j00], d_inv[j01], d_inv[j10], d_inv[j11] };
    const float eps = EPS_F;
    unsigned barcnt = 0;
    float acc[8];
    float sp[8];   // prefetched fp32 state values
    float xp[8];   // prefetched x[t+1] values
    const bool epi = (kq == 0);
    const bool has_x = (jbase < IN_W);

    for (int t = 0; t < SEQ; t++) {
        const int cur = t & 1, nxt = cur ^ 1;

        // ---- prefetch epilogue operands for this step (available since last barrier)
        if (epi) {
            const float* Sc = d_Sf[cur];
            ld2cg(sp[0], sp[1], Sc + gr0 * SW + j00);
            ld2cg(sp[2], sp[3], Sc + gr1 * SW + j00);
            ld2cg(sp[4], sp[5], Sc + gr0 * SW + j10);
            ld2cg(sp[6], sp[7], Sc + gr1 * SW + j10);
            if (has_x && t < SEQ - 1) {
                const float* xb = x + (size_t)(t + 1) * BATCH * IN_W;
                ld2cg(xp[0], xp[1], xb + gr0 * IN_W + j00);
                ld2cg(xp[2], xp[3], xb + gr1 * IN_W + j00);
                ld2cg(xp[4], xp[5], xb + gr0 * IN_W + j10);
                ld2cg(xp[6], xp[7], xb + gr1 * IN_W + j10);
            }
        }

        // ================= phase 1: h = relu(S @ W1^T + b1) =================
        gemm_phase(d_Sh[cur] + (size_t)rbase * SW, Act, actU32, w1U32, tid, m, aOff, bOff, acc);
        kreduce(Red, m, kq, lane, acc);
        if (epi) {
            __nv_bfloat162* Hp = reinterpret_cast<__nv_bfloat162*>(d_H);
            float h0 = fmaxf(acc[0] + bb1[0], 0.f), h1 = fmaxf(acc[1] + bb1[1], 0.f);
            float h2 = fmaxf(acc[2] + bb1[0], 0.f), h3 = fmaxf(acc[3] + bb1[1], 0.f);
            float h4 = fmaxf(acc[4] + bb1[2], 0.f), h5 = fmaxf(acc[5] + bb1[3], 0.f);
            float h6 = fmaxf(acc[6] + bb1[2], 0.f), h7 = fmaxf(acc[7] + bb1[3], 0.f);
            Hp[(gr0 * SW + j00) >> 1] = __floats2bfloat162_rn(h0, h1);
            Hp[(gr1 * SW + j00) >> 1] = __floats2bfloat162_rn(h2, h3);
            Hp[(gr0 * SW + j10) >> 1] = __floats2bfloat162_rn(h4, h5);
            Hp[(gr1 * SW + j10) >> 1] = __floats2bfloat162_rn(h6, h7);
        }
        gbar(barcnt, bh, cg);

        // ================= phase 2: y = h @ W2^T + b2 ; fused update ========
        gemm_phase(d_H + (size_t)rbase * SW, Act, actU32, w2U32, tid, m, aOff, bOff, acc);
        kreduce(Red, m, kq, lane, acc);
        if (epi) {
            float y[8];
            y[0] = acc[0] + bb2[0]; y[1] = acc[1] + bb2[1];
            y[2] = acc[2] + bb2[0]; y[3] = acc[3] + bb2[1];
            y[4] = acc[4] + bb2[2]; y[5] = acc[5] + bb2[3];
            y[6] = acc[6] + bb2[2]; y[7] = acc[7] + bb2[3];
            const int rr[8] = { gr0, gr0, gr1, gr1, gr0, gr0, gr1, gr1 };
            const int jj[8] = { j00, j01, j00, j01, j10, j11, j10, j11 };
            const int pp[8] = { ip[0], ip[1], ip[0], ip[1], ip[2], ip[3], ip[2], ip[3] };
            float nv[8];
#pragma unroll
            for (int u = 0; u < 8; u++) nv[u] = LIN_F * sp[u] + eps * y[u];
            if (t < SEQ - 1) {
                if (has_x) {
#pragma unroll
                    for (int u = 0; u < 8; u++) nv[u] += xp[u];
                }
                float* Sn = d_Sf[nxt];
                __nv_bfloat16* Shn = d_Sh[nxt];
#pragma unroll
                for (int u = 0; u < 8; u++) {
                    int a = rr[u] * SW + pp[u];
                    Sn[a]  = nv[u];
                    Shn[a] = __float2bfloat16(nv[u]);
                }
            } else {
#pragma unroll
                for (int u = 0; u < 8; u++) {
                    int b = rr[u], i = jj[u];
                    float v = nv[u];
                    if (out_size == BATCH * (OUT_W + SW)) {           // (outputs, last)
                        out[BATCH * OUT_W + b * SW + i] = v;
                        if (i >= SW - OUT_W) out[b * OUT_W + (i - (SW - OUT_W))] = v;
                    } else if (out_size == BATCH * SW) {              // last only
                        out[b * SW + i] = v;
                    } else {                                          // outputs only
                        if (i >= SW - OUT_W) out[b * OUT_W + (i - (SW - OUT_W))] = v;
                    }
                }
            }
        }
        gbar(barcnt, bh, cg);
    }
}

// ---------------- launch ----------------
extern "C" void kernel_launch(void* const* d_in, const int* in_sizes, int n_in,
                              void* d_out, int out_size) {
    const float* x    = (const float*)d_in[0];
    const float* init = (const float*)d_in[1];
    const int*   rp   = (const int*)  d_in[2];
    const float* W1   = (const float*)d_in[3];
    const float* b1   = (const float*)d_in[4];
    const float* W2   = (const float*)d_in[5];
    const float* b2   = (const float*)d_in[6];

    setup_kernel<<<64, 256>>>(x, init, rp);

    const int smem_bytes = (2 * JS * PADC + ROWS * PADC) * (int)sizeof(__nv_bfloat16)
                         + 6 * 256 * (int)sizeof(float);
    cudaFuncSetAttribute(resrnn_kernel, cudaFuncAttributeMaxDynamicSharedMemorySize, smem_bytes);
    resrnn_kernel<<<P_CTAS, NTHREADS, smem_bytes>>>(x, W1, b1, W2, b2,
                                                    (float*)d_out, out_size);
}

// round 7
// speedup vs baseline: 1.3086x; 1.0202x over previous
#include <cuda_runtime.h>
#include <cuda_bf16.h>
#include <cstdint>

// ---------------- problem constants ----------------
#define SEQ    512
#define BATCH  64
#define IN_W   256
#define SW     1024
#define OUT_W  256

// ---------------- kernel config --------------------
#define P_CTAS   128     // 2 independent batch-halves x 64 col-groups
#define HALF_CTAS 64
#define NTHREADS 256     // 8 warps = 2 m-tiles x 4 k-splits
#define JS       16      // output columns per CTA
#define ROWS     32      // batch rows per CTA
#define PADC     1032    // padded row stride in elems (2064B = 16 mod 128 -> LDSM conflict-free)

#define LIN_F 0.99999f
__device__ __constant__ float EPS_F = (float)(1.0 - 0.99999);

// ---------------- global scratch ----------------
__device__ float          d_Uf[2][BATCH * SW];   // fp32 unpermuted stream u_t (ping-pong)
__device__ __nv_bfloat16  d_Uh[2][BATCH * SW];   // bf16 shadow of u_t
__device__ __nv_bfloat16  d_H[BATCH * SW];       // hidden activations (bf16)
__device__ int            d_inv[SW];             // inverse permutation (rp[inv[q]] = q)
__device__ unsigned       d_cnt[16 * 64];        // per-half distributed barrier counters

// ---------------- helpers ----------------
static __device__ __forceinline__ unsigned smem_u32(const void* p) {
    return (unsigned)__cvta_generic_to_shared(p);
}

// batch-half-scoped grid barrier: 8 counters per half, 8 arrivals each
__device__ __forceinline__ void gbar(unsigned& barcnt, int bh, int cg) {
    __syncthreads();
    if (threadIdx.x == 0) {
        unsigned* base = d_cnt + bh * 8 * 64;
        unsigned* cnt  = base + (cg & 7) * 64;
        asm volatile("red.release.gpu.global.add.u32 [%0], 1;" :: "l"(cnt) : "memory");
        const unsigned target = (barcnt + 1u) * (unsigned)HALF_CTAS;
        unsigned total;
        do {
            total = 0;
#pragma unroll
            for (int i = 0; i < 8; i++) {
                unsigned v;
                asm volatile("ld.acquire.gpu.u32 %0, [%1];" : "=r"(v) : "l"(base + i * 64) : "memory");
                total += v;
            }
        } while (total < target);
    }
    barcnt++;
    __syncthreads();
}

static __device__ __forceinline__ void ldsm4(uint32_t& r0, uint32_t& r1, uint32_t& r2, uint32_t& r3,
                                             unsigned addr) {
    asm volatile("ldmatrix.sync.aligned.m8n8.x4.shared.b16 {%0,%1,%2,%3}, [%4];"
                 : "=r"(r0), "=r"(r1), "=r"(r2), "=r"(r3) : "r"(addr));
}

static __device__ __forceinline__ void mma16816(float* c,
                                                uint32_t a0, uint32_t a1, uint32_t a2, uint32_t a3,
                                                uint32_t b0, uint32_t b1) {
    asm("mma.sync.aligned.m16n8k16.row.col.f32.bf16.bf16.f32 "
        "{%0,%1,%2,%3}, {%4,%5,%6,%7}, {%8,%9}, {%0,%1,%2,%3};\n"
        : "+f"(c[0]), "+f"(c[1]), "+f"(c[2]), "+f"(c[3])
        : "r"(a0), "r"(a1), "r"(a2), "r"(a3), "r"(b0), "r"(b1));
}

static __device__ __forceinline__ void ld2cg(float& a, float& b, const float* p) {
    asm volatile("ld.global.cg.v2.f32 {%0,%1}, [%2];" : "=f"(a), "=f"(b) : "l"(p));
}
static __device__ __forceinline__ float ldcg_f(const float* p) {
    float v;
    asm volatile("ld.global.cg.f32 %0, [%1];" : "=f"(v) : "l"(p));
    return v;
}
static __device__ __forceinline__ void st2cg(float* p, float a, float b) {
    asm volatile("st.global.cg.v2.f32 [%0], {%1,%2};" :: "l"(p), "f"(a), "f"(b));
}

// MMA over this warp's k-quarter with dual accumulators (chain depth 8)
static __device__ __forceinline__ void mma_quarter(unsigned aA, unsigned aB, float* acc) {
    float accB[8];
#pragma unroll
    for (int u = 0; u < 8; u++) { acc[u] = 0.f; accB[u] = 0.f; }
#pragma unroll
    for (int ki = 0; ki < 16; ki += 2) {
        uint32_t a0, a1, a2, a3, b0, b1, b2, b3;
        ldsm4(a0, a1, a2, a3, aA + ki * 32);
        ldsm4(b0, b1, b2, b3, aB + ki * 32);
        mma16816(acc,     a0, a1, a2, a3, b0, b2);
        mma16816(acc + 4, a0, a1, a2, a3, b1, b3);
        ldsm4(a0, a1, a2, a3, aA + (ki + 1) * 32);
        ldsm4(b0, b1, b2, b3, aB + (ki + 1) * 32);
        mma16816(accB,     a0, a1, a2, a3, b0, b2);
        mma16816(accB + 4, a0, a1, a2, a3, b1, b3);
    }
#pragma unroll
    for (int u = 0; u < 8; u++) acc[u] += accB[u];
}

// one phase GEMM: pipelined copy (two 16-row chunks) + k-split MMA
static __device__ __forceinline__ void gemm_phase(const __nv_bfloat16* __restrict__ actg,
                                                  __nv_bfloat16* Act, unsigned actU32,
                                                  unsigned wsU32,
                                                  int tid, int m, unsigned aOff, unsigned bOff,
                                                  float* acc) {
#pragma unroll
    for (int c = 0; c < 2; c++) {
#pragma unroll
        for (int s = 0; s < 8; s++) {
            int e = tid + s * NTHREADS;          // 0..2047
            int row = c * 16 + (e >> 7);
            int seg = e & 127;
            unsigned dst = smem_u32(Act + row * PADC + seg * 8);
            const void* src = (const void*)(actg + row * SW + seg * 8);
            asm volatile("cp.async.cg.shared.global [%0], [%1], 16;\n" :: "r"(dst), "l"(src));
        }
        asm volatile("cp.async.commit_group;\n" ::: "memory");
    }
    unsigned aA = actU32 + aOff;
    unsigned aB = wsU32 + bOff;
    asm volatile("cp.async.wait_group 1;\n" ::: "memory");
    __syncthreads();                              // rows 0-15 visible
    if (m == 0) mma_quarter(aA, aB, acc);
    asm volatile("cp.async.wait_group 0;\n" ::: "memory");
    __syncthreads();                              // rows 16-31 visible
    if (m == 1) mma_quarter(aA, aB, acc);
}

// cross-warp k-reduction (4-way): kq>0 store, kq==0 add. One syncthreads.
static __device__ __forceinline__ void kreduce(float* Red, int m, int kq, int lane, float* acc) {
    if (kq > 0) {
        float* slot = Red + ((kq - 1) * 2 + m) * 256;
#pragma unroll
        for (int u = 0; u < 8; u++) slot[u * 32 + lane] = acc[u];
    }
    __syncthreads();
    if (kq == 0) {
#pragma unroll
        for (int k = 0; k < 3; k++) {
            const float* slot = Red + (k * 2 + m) * 256;
#pragma unroll
            for (int u = 0; u < 8; u++) acc[u] += slot[u * 32 + lane];
        }
    }
}

// ---------------- setup: inverse perm, u0 (unpermuted!), barrier reset ----------------
__global__ void setup_kernel(const float* __restrict__ x,
                             const float* __restrict__ init,
                             const int* __restrict__ rp) {
    int tid = blockIdx.x * blockDim.x + threadIdx.x;
    if (tid < 16 * 64) d_cnt[tid] = 0u;
    if (tid < SW) d_inv[rp[tid]] = tid;
    const float eps = EPS_F;
    for (int e = tid; e < BATCH * SW; e += gridDim.x * blockDim.x) {
        int b = e >> 10, p = e & (SW - 1);
        float v = eps * init[p];              // u0 = stream0 + x0 (raw index space)
        if (p < IN_W) v += x[b * IN_W + p];
        d_Uf[0][b * SW + p] = v;
        d_Uh[0][b * SW + p] = __float2bfloat16(v);
    }
}

// ---------------- persistent RNN kernel ----------------
__global__ void __launch_bounds__(NTHREADS, 1)
resrnn_kernel(const float* __restrict__ x, const int* __restrict__ rp,
              const float* __restrict__ W1, const float* __restrict__ b1,
              const float* __restrict__ W2, const float* __restrict__ b2,
              float* __restrict__ out, int out_size) {
    extern __shared__ __nv_bfloat16 smem[];
    __nv_bfloat16* W1s = smem;                       // [JS][PADC]  (column-permuted W1!)
    __nv_bfloat16* W2s = smem + JS * PADC;           // [JS][PADC]
    __nv_bfloat16* Act = smem + 2 * JS * PADC;       // [ROWS][PADC]
    float*         Red = reinterpret_cast<float*>(smem + 2 * JS * PADC + ROWS * PADC); // [6][256]

    const int tid   = threadIdx.x;
    const int cta   = blockIdx.x;
    const int cg    = cta & 63;          // column group
    const int bh    = cta >> 6;          // batch half (independent recurrence)
    const int jbase = cg * JS;
    const int rbase = bh * ROWS;

    // ---- stage inverse perm in smem (reuse Act region), then load weights ----
    {
        int* invs = reinterpret_cast<int*>(Act);
        for (int e = tid; e < SW; e += NTHREADS) invs[e] = d_inv[e];
        __syncthreads();
        for (int e = tid; e < JS * SW; e += NTHREADS) {
            int n = e >> 10, q = e & (SW - 1);
            // W1p[j,q] = W1[j, inv[q]]  -> GEMM1 consumes UNpermuted u directly
            W1s[n * PADC + q] = __float2bfloat16(W1[(size_t)(jbase + n) * SW + invs[q]]);
            W2s[n * PADC + q] = __float2bfloat16(W2[(size_t)(jbase + n) * SW + q]);
        }
        __syncthreads();
    }

    // ---- per-thread static coordinates ----
    const int warp = tid >> 5, lane = tid & 31;
    const int m  = warp & 1;             // m-tile (16 rows)
    const int kq = warp >> 1;            // k-quarter (256 elems)
    const int g  = lane >> 2, quad = lane & 3, tc = quad * 2;

    const unsigned aOff = (unsigned)((m * 16 + (lane & 15)) * (PADC * 2) + ((lane >> 4) << 4) + kq * 512);
    const unsigned bOff = (unsigned)(((lane & 15)) * (PADC * 2) + ((lane >> 4) << 4) + kq * 512);
    const unsigned actU32 = smem_u32(Act);
    const unsigned w1U32  = smem_u32(W1s);
    const unsigned w2U32  = smem_u32(W2s);

    // epilogue coordinates (kq==0 warps)
    const int r0 = m * 16 + g, r1 = r0 + 8;
    const int gr0 = rbase + r0, gr1 = rbase + r1;
    const int j00 = jbase + tc,     j01 = j00 + 1;
    const int j10 = jbase + 8 + tc, j11 = j10 + 1;
    const float bb1[4] = { b1[j00], b1[j01], b1[j10], b1[j11] };
    const float bb2[4] = { b2[j00], b2[j01], b2[j10], b2[j11] };
    // gather sources for the update: u_t[rp[i]] for this thread's output cols i
    const int rpj[4] = { rp[j00], rp[j01], rp[j10], rp[j11] };
    const float eps = EPS_F;
    unsigned barcnt = 0;
    float acc[8];
    float sp[8];   // prefetched u_t[gr, rp[i]]
    float xf[8];   // prefetched x[t+1]
    const bool epi = (kq == 0);
    const bool has_x = (jbase < IN_W);

    for (int t = 0; t < SEQ; t++) {
        const int cur = t & 1, nxt = cur ^ 1;

        // ---- prefetch epilogue operands (u_t ready since last barrier) ----
        if (epi) {
            const float* Uc = d_Uf[cur];
            sp[0] = ldcg_f(Uc + gr0 * SW + rpj[0]);
            sp[1] = ldcg_f(Uc + gr0 * SW + rpj[1]);
            sp[2] = ldcg_f(Uc + gr1 * SW + rpj[0]);
            sp[3] = ldcg_f(Uc + gr1 * SW + rpj[1]);
            sp[4] = ldcg_f(Uc + gr0 * SW + rpj[2]);
            sp[5] = ldcg_f(Uc + gr0 * SW + rpj[3]);
            sp[6] = ldcg_f(Uc + gr1 * SW + rpj[2]);
            sp[7] = ldcg_f(Uc + gr1 * SW + rpj[3]);
            if (has_x && t < SEQ - 1) {
                const float* xb = x + (size_t)(t + 1) * BATCH * IN_W;
                ld2cg(xf[0], xf[1], xb + gr0 * IN_W + j00);
                ld2cg(xf[2], xf[3], xb + gr1 * IN_W + j00);
                ld2cg(xf[4], xf[5], xb + gr0 * IN_W + j10);
                ld2cg(xf[6], xf[7], xb + gr1 * IN_W + j10);
            }
        }

        // ================= phase 1: h = relu(u @ W1p^T + b1) =================
        gemm_phase(d_Uh[cur] + (size_t)rbase * SW, Act, actU32, w1U32, tid, m, aOff, bOff, acc);
        kreduce(Red, m, kq, lane, acc);
        if (epi) {
            __nv_bfloat162* Hp = reinterpret_cast<__nv_bfloat162*>(d_H);
            float h0 = fmaxf(acc[0] + bb1[0], 0.f), h1 = fmaxf(acc[1] + bb1[1], 0.f);
            float h2 = fmaxf(acc[2] + bb1[0], 0.f), h3 = fmaxf(acc[3] + bb1[1], 0.f);
            float h4 = fmaxf(acc[4] + bb1[2], 0.f), h5 = fmaxf(acc[5] + bb1[3], 0.f);
            float h6 = fmaxf(acc[6] + bb1[2], 0.f), h7 = fmaxf(acc[7] + bb1[3], 0.f);
            Hp[(gr0 * SW + j00) >> 1] = __floats2bfloat162_rn(h0, h1);
            Hp[(gr1 * SW + j00) >> 1] = __floats2bfloat162_rn(h2, h3);
            Hp[(gr0 * SW + j10) >> 1] = __floats2bfloat162_rn(h4, h5);
            Hp[(gr1 * SW + j10) >> 1] = __floats2bfloat162_rn(h6, h7);
        }
        gbar(barcnt, bh, cg);

        // ================= phase 2: y = h @ W2^T + b2 ; coalesced update ====
        gemm_phase(d_H + (size_t)rbase * SW, Act, actU32, w2U32, tid, m, aOff, bOff, acc);
        kreduce(Red, m, kq, lane, acc);
        if (epi) {
            float nv[8];
            nv[0] = LIN_F * sp[0] + eps * (acc[0] + bb2[0]);
            nv[1] = LIN_F * sp[1] + eps * (acc[1] + bb2[1]);
            nv[2] = LIN_F * sp[2] + eps * (acc[2] + bb2[0]);
            nv[3] = LIN_F * sp[3] + eps * (acc[3] + bb2[1]);
            nv[4] = LIN_F * sp[4] + eps * (acc[4] + bb2[2]);
            nv[5] = LIN_F * sp[5] + eps * (acc[5] + bb2[3]);
            nv[6] = LIN_F * sp[6] + eps * (acc[6] + bb2[2]);
            nv[7] = LIN_F * sp[7] + eps * (acc[7] + bb2[3]);
            if (t < SEQ - 1) {
                if (has_x) {
#pragma unroll
                    for (int u = 0; u < 8; u++) nv[u] += xf[u];
                }
                float* Un = d_Uf[nxt];
                __nv_bfloat162* Uhn = reinterpret_cast<__nv_bfloat162*>(d_Uh[nxt]);
                st2cg(Un + gr0 * SW + j00, nv[0], nv[1]);
                st2cg(Un + gr1 * SW + j00, nv[2], nv[3]);
                st2cg(Un + gr0 * SW + j10, nv[4], nv[5]);
                st2cg(Un + gr1 * SW + j10, nv[6], nv[7]);
                Uhn[(gr0 * SW + j00) >> 1] = __floats2bfloat162_rn(nv[0], nv[1]);
                Uhn[(gr1 * SW + j00) >> 1] = __floats2bfloat162_rn(nv[2], nv[3]);
                Uhn[(gr0 * SW + j10) >> 1] = __floats2bfloat162_rn(nv[4], nv[5]);
                Uhn[(gr1 * SW + j10) >> 1] = __floats2bfloat162_rn(nv[6], nv[7]);
            } else {
                // final step: nv = stream_512[i] (no x). Emit per out_size layout.
                const int rr[8] = { gr0, gr0, gr1, gr1, gr0, gr0, gr1, gr1 };
                const int jj[8] = { j00, j01, j00, j01, j10, j11, j10, j11 };
#pragma unroll
                for (int u = 0; u < 8; u++) {
                    int b = rr[u], i = jj[u];
                    float v = nv[u];
                    if (out_size == BATCH * (OUT_W + SW)) {           // (outputs, last)
                        out[BATCH * OUT_W + b * SW + i] = v;
                        if (i >= SW - OUT_W) out[b * OUT_W + (i - (SW - OUT_W))] = v;
                    } else if (out_size == BATCH * SW) {              // last only
                        out[b * SW + i] = v;
                    } else {                                          // outputs only
                        if (i >= SW - OUT_W) out[b * OUT_W + (i - (SW - OUT_W))] = v;
                    }
                }
            }
        }
        gbar(barcnt, bh, cg);
    }
}

// ---------------- launch ----------------
extern "C" void kernel_launch(void* const* d_in, const int* in_sizes, int n_in,
                              void* d_out, int out_size) {
    const float* x    = (const float*)d_in[0];
    const float* init = (const float*)d_in[1];
    const int*   rp   = (const int*)  d_in[2];
    const float* W1   = (const float*)d_in[3];
    const float* b1   = (const float*)d_in[4];
    const float* W2   = (const float*)d_in[5];
    const float* b2   = (const float*)d_in[6];

    setup_kernel<<<64, 256>>>(x, init, rp);

    const int smem_bytes = (2 * JS * PADC + ROWS * PADC) * (int)sizeof(__nv_bfloat16)
                         + 6 * 256 * (int)sizeof(float);
    cudaFuncSetAttribute(resrnn_kernel, cudaFuncAttributeMaxDynamicSharedMemorySize, smem_bytes);
    resrnn_kernel<<<P_CTAS, NTHREADS, smem_bytes>>>(x, rp, W1, b1, W2, b2,
                                                    (float*)d_out, out_size);
}

// round 8
// speedup vs baseline: 1.4222x; 1.0868x over previous
#include <cuda_runtime.h>
#include <cuda_bf16.h>
#include <cstdint>

// ---------------- problem constants ----------------
#define SEQ    512
#define BATCH  64
#define IN_W   256
#define SW     1024
#define OUT_W  256

// ---------------- kernel config --------------------
#define P_CTAS   256     // 4 row-quarters x 64 col-groups
#define DOM_CTAS 64      // CTAs per barrier domain (one quarter)
#define NTHREADS 256     // 8 warps = 2 n-halves x 4 k-quarters
#define JS       16      // output columns per CTA
#define QROWS    16      // batch rows per CTA (one quarter)
#define PADC     1032    // padded row stride in elems (2064B = 16 mod 128 -> LDSM conflict-free)

#define LIN_F 0.99999f
__device__ __constant__ float EPS_F = (float)(1.0 - 0.99999);

// ---------------- global scratch ----------------
__device__ float          d_Uf[2][BATCH * SW];   // fp32 unpermuted stream u_t (ping-pong)
__device__ __nv_bfloat16  d_Uh[2][BATCH * SW];   // bf16 shadow of u_t
__device__ __nv_bfloat16  d_H[BATCH * SW];       // hidden activations (bf16)
__device__ int            d_inv[SW];             // inverse permutation (rp[inv[q]] = q)
__device__ unsigned       d_cnt[32 * 64];        // 4 domains x 8 distributed counters (256B apart)

// ---------------- helpers ----------------
static __device__ __forceinline__ unsigned smem_u32(const void* p) {
    return (unsigned)__cvta_generic_to_shared(p);
}

// quarter-scoped grid barrier: 8 counters per domain, 8 arrivals each
__device__ __forceinline__ void gbar(unsigned& barcnt, int qr, int cg) {
    __syncthreads();
    if (threadIdx.x == 0) {
        unsigned* base = d_cnt + qr * 8 * 64;
        unsigned* cnt  = base + (cg & 7) * 64;
        asm volatile("red.release.gpu.global.add.u32 [%0], 1;" :: "l"(cnt) : "memory");
        const unsigned target = (barcnt + 1u) * (unsigned)DOM_CTAS;
        unsigned total;
        do {
            total = 0;
#pragma unroll
            for (int i = 0; i < 8; i++) {
                unsigned v;
                asm volatile("ld.acquire.gpu.u32 %0, [%1];" : "=r"(v) : "l"(base + i * 64) : "memory");
                total += v;
            }
        } while (total < target);
    }
    barcnt++;
    __syncthreads();
}

static __device__ __forceinline__ void ldsm4(uint32_t& r0, uint32_t& r1, uint32_t& r2, uint32_t& r3,
                                             unsigned addr) {
    asm volatile("ldmatrix.sync.aligned.m8n8.x4.shared.b16 {%0,%1,%2,%3}, [%4];"
                 : "=r"(r0), "=r"(r1), "=r"(r2), "=r"(r3) : "r"(addr));
}

static __device__ __forceinline__ void mma16816(float* c,
                                                uint32_t a0, uint32_t a1, uint32_t a2, uint32_t a3,
                                                uint32_t b0, uint32_t b1) {
    asm("mma.sync.aligned.m16n8k16.row.col.f32.bf16.bf16.f32 "
        "{%0,%1,%2,%3}, {%4,%5,%6,%7}, {%8,%9}, {%0,%1,%2,%3};\n"
        : "+f"(c[0]), "+f"(c[1]), "+f"(c[2]), "+f"(c[3])
        : "r"(a0), "r"(a1), "r"(a2), "r"(a3), "r"(b0), "r"(b1));
}

static __device__ __forceinline__ void ld2cg(float& a, float& b, const float* p) {
    asm volatile("ld.global.cg.v2.f32 {%0,%1}, [%2];" : "=f"(a), "=f"(b) : "l"(p));
}
static __device__ __forceinline__ float ldcg_f(const float* p) {
    float v;
    asm volatile("ld.global.cg.f32 %0, [%1];" : "=f"(v) : "l"(p));
    return v;
}
static __device__ __forceinline__ void st2cg(float* p, float a, float b) {
    asm volatile("st.global.cg.v2.f32 [%0], {%1,%2};" :: "l"(p), "f"(a), "f"(b));
}

// one phase GEMM: copy act[16x1024] into padded smem, then per-warp
// acc[4] = m16 n8 k256 with dual accumulators (chain depth 8).
static __device__ __forceinline__ void gemm_phase(const __nv_bfloat16* __restrict__ actg,
                                                  __nv_bfloat16* Act, unsigned aA, unsigned aB,
                                                  int tid, int nhalf, float* acc) {
    // ---- bulk copy 32KB: 8 x cp.async.cg(16B) per thread ----
#pragma unroll
    for (int s = 0; s < 8; s++) {
        int e = tid + s * NTHREADS;          // 0..2047
        int row = e >> 7;                    // 0..15
        int seg = e & 127;
        unsigned dst = smem_u32(Act + row * PADC + seg * 8);
        const void* src = (const void*)(actg + row * SW + seg * 8);
        asm volatile("cp.async.cg.shared.global [%0], [%1], 16;\n" :: "r"(dst), "l"(src));
    }
    asm volatile("cp.async.commit_group;\n" ::: "memory");
    asm volatile("cp.async.wait_group 0;\n" ::: "memory");
    __syncthreads();

    float accB[4];
#pragma unroll
    for (int u = 0; u < 4; u++) { acc[u] = 0.f; accB[u] = 0.f; }
#pragma unroll
    for (int ki = 0; ki < 16; ki += 2) {
        uint32_t a0, a1, a2, a3, b0, b1, b2, b3;
        ldsm4(a0, a1, a2, a3, aA + ki * 32);
        ldsm4(b0, b1, b2, b3, aB + ki * 32);
        if (nhalf == 0) mma16816(acc, a0, a1, a2, a3, b0, b2);
        else            mma16816(acc, a0, a1, a2, a3, b1, b3);
        ldsm4(a0, a1, a2, a3, aA + (ki + 1) * 32);
        ldsm4(b0, b1, b2, b3, aB + (ki + 1) * 32);
        if (nhalf == 0) mma16816(accB, a0, a1, a2, a3, b0, b2);
        else            mma16816(accB, a0, a1, a2, a3, b1, b3);
    }
#pragma unroll
    for (int u = 0; u < 4; u++) acc[u] += accB[u];
}

// cross-warp k-reduction (4-way): kq>0 store, kq==0 add. One syncthreads.
static __device__ __forceinline__ void kreduce(float* Red, int nhalf, int kq, int lane, float* acc) {
    if (kq > 0) {
        float* slot = Red + ((kq - 1) * 2 + nhalf) * 128;
#pragma unroll
        for (int u = 0; u < 4; u++) slot[u * 32 + lane] = acc[u];
    }
    __syncthreads();
    if (kq == 0) {
#pragma unroll
        for (int k = 0; k < 3; k++) {
            const float* slot = Red + (k * 2 + nhalf) * 128;
#pragma unroll
            for (int u = 0; u < 4; u++) acc[u] += slot[u * 32 + lane];
        }
    }
}

// ---------------- setup: inverse perm, u0 (unpermuted), barrier reset ----------------
__global__ void setup_kernel(const float* __restrict__ x,
                             const float* __restrict__ init,
                             const int* __restrict__ rp) {
    int tid = blockIdx.x * blockDim.x + threadIdx.x;
    if (tid < 32 * 64) d_cnt[tid] = 0u;
    if (tid < SW) d_inv[rp[tid]] = tid;
    const float eps = EPS_F;
    for (int e = tid; e < BATCH * SW; e += gridDim.x * blockDim.x) {
        int b = e >> 10, p = e & (SW - 1);
        float v = eps * init[p];              // u0 = stream0 + x0 (raw index space)
        if (p < IN_W) v += x[b * IN_W + p];
        d_Uf[0][b * SW + p] = v;
        d_Uh[0][b * SW + p] = __float2bfloat16(v);
    }
}

// ---------------- persistent RNN kernel ----------------
__global__ void __launch_bounds__(NTHREADS)
resrnn_kernel(const float* __restrict__ x, const int* __restrict__ rp,
              const float* __restrict__ W1, const float* __restrict__ b1,
              const float* __restrict__ W2, const float* __restrict__ b2,
              float* __restrict__ out, int out_size) {
    extern __shared__ __nv_bfloat16 smem[];
    __nv_bfloat16* W1s = smem;                       // [JS][PADC]  (column-permuted W1)
    __nv_bfloat16* W2s = smem + JS * PADC;           // [JS][PADC]
    __nv_bfloat16* Act = smem + 2 * JS * PADC;       // [QROWS][PADC]
    float*         Red = reinterpret_cast<float*>(smem + 2 * JS * PADC + QROWS * PADC); // [6][128]

    const int tid   = threadIdx.x;
    const int cta   = blockIdx.x;
    const int cg    = cta & 63;          // column group
    const int qr    = cta >> 6;          // row quarter (independent recurrence + barrier domain)
    const int jbase = cg * JS;
    const int rbase = qr * QROWS;

    // ---- stage inverse perm in smem (reuse Act region), then load weights ----
    {
        int* invs = reinterpret_cast<int*>(Act);
        for (int e = tid; e < SW; e += NTHREADS) invs[e] = d_inv[e];
        __syncthreads();
        for (int e = tid; e < JS * SW; e += NTHREADS) {
            int n = e >> 10, q = e & (SW - 1);
            // W1p[j,q] = W1[j, inv[q]]  -> GEMM1 consumes UNpermuted u directly
            W1s[n * PADC + q] = __float2bfloat16(W1[(size_t)(jbase + n) * SW + invs[q]]);
            W2s[n * PADC + q] = __float2bfloat16(W2[(size_t)(jbase + n) * SW + q]);
        }
        __syncthreads();
    }

    // ---- per-thread static coordinates ----
    const int warp = tid >> 5, lane = tid & 31;
    const int nhalf = warp & 1;          // 8-column half of this CTA's 16 cols
    const int kq    = warp >> 1;         // k-quarter (256 elems)
    const int g  = lane >> 2, tc = (lane & 3) * 2;

    const unsigned aOff = (unsigned)((lane & 15) * (PADC * 2) + ((lane >> 4) << 4) + kq * 512);
    const unsigned aA = smem_u32(Act) + aOff;
    const unsigned bW1 = smem_u32(W1s) + aOff;
    const unsigned bW2 = smem_u32(W2s) + aOff;

    // epilogue coordinates (kq==0 warps handle all 16 rows x their 8 cols)
    const int r0 = g, r1 = g + 8;
    const int gr0 = rbase + r0, gr1 = rbase + r1;
    const int j0 = jbase + nhalf * 8 + tc, j1 = j0 + 1;
    const float bb1_0 = b1[j0], bb1_1 = b1[j1];
    const float bb2_0 = b2[j0], bb2_1 = b2[j1];
    const int rp0 = rp[j0], rp1 = rp[j1];   // gather sources: u_t[·, rp[j]]
    const float eps = EPS_F;
    unsigned barcnt = 0;
    float acc[4];
    float sp[4];   // prefetched u_t gathers
    float xf[4];   // prefetched x[t+1]
    const bool epi = (kq == 0);
    const bool has_x = (jbase < IN_W);

    for (int t = 0; t < SEQ; t++) {
        const int cur = t & 1, nxt = cur ^ 1;

        // ---- prefetch epilogue operands (u_t ready since last barrier) ----
        if (epi) {
            const float* Uc = d_Uf[cur];
            sp[0] = ldcg_f(Uc + gr0 * SW + rp0);
            sp[1] = ldcg_f(Uc + gr0 * SW + rp1);
            sp[2] = ldcg_f(Uc + gr1 * SW + rp0);
            sp[3] = ldcg_f(Uc + gr1 * SW + rp1);
            if (has_x && t < SEQ - 1) {
                const float* xb = x + (size_t)(t + 1) * BATCH * IN_W;
                ld2cg(xf[0], xf[1], xb + gr0 * IN_W + j0);
                ld2cg(xf[2], xf[3], xb + gr1 * IN_W + j0);
            }
        }

        // ================= phase 1: h = relu(u @ W1p^T + b1) =================
        gemm_phase(d_Uh[cur] + (size_t)rbase * SW, Act, aA, bW1, tid, nhalf, acc);
        kreduce(Red, nhalf, kq, lane, acc);
        if (epi) {
            __nv_bfloat162* Hp = reinterpret_cast<__nv_bfloat162*>(d_H);
            float h0 = fmaxf(acc[0] + bb1_0, 0.f), h1 = fmaxf(acc[1] + bb1_1, 0.f);
            float h2 = fmaxf(acc[2] + bb1_0, 0.f), h3 = fmaxf(acc[3] + bb1_1, 0.f);
            Hp[(gr0 * SW + j0) >> 1] = __floats2bfloat162_rn(h0, h1);
            Hp[(gr1 * SW + j0) >> 1] = __floats2bfloat162_rn(h2, h3);
        }
        gbar(barcnt, qr, cg);

        // ================= phase 2: y = h @ W2^T + b2 ; coalesced update ====
        gemm_phase(d_H + (size_t)rbase * SW, Act, aA, bW2, tid, nhalf, acc);
        kreduce(Red, nhalf, kq, lane, acc);
        if (epi) {
            float nv0 = LIN_F * sp[0] + eps * (acc[0] + bb2_0);
            float nv1 = LIN_F * sp[1] + eps * (acc[1] + bb2_1);
            float nv2 = LIN_F * sp[2] + eps * (acc[2] + bb2_0);
            float nv3 = LIN_F * sp[3] + eps * (acc[3] + bb2_1);
            if (t < SEQ - 1) {
                if (has_x) { nv0 += xf[0]; nv1 += xf[1]; nv2 += xf[2]; nv3 += xf[3]; }
                float* Un = d_Uf[nxt];
                __nv_bfloat162* Uhn = reinterpret_cast<__nv_bfloat162*>(d_Uh[nxt]);
                st2cg(Un + gr0 * SW + j0, nv0, nv1);
                st2cg(Un + gr1 * SW + j0, nv2, nv3);
                Uhn[(gr0 * SW + j0) >> 1] = __floats2bfloat162_rn(nv0, nv1);
                Uhn[(gr1 * SW + j0) >> 1] = __floats2bfloat162_rn(nv2, nv3);
            } else {
                const int rr[4] = { gr0, gr0, gr1, gr1 };
                const int jj[4] = { j0, j1, j0, j1 };
                const float vv[4] = { nv0, nv1, nv2, nv3 };
#pragma unroll
                for (int u = 0; u < 4; u++) {
                    int b = rr[u], i = jj[u];
                    float v = vv[u];
                    if (out_size == BATCH * (OUT_W + SW)) {           // (outputs, last)
                        out[BATCH * OUT_W + b * SW + i] = v;
                        if (i >= SW - OUT_W) out[b * OUT_W + (i - (SW - OUT_W))] = v;
                    } else if (out_size == BATCH * SW) {              // last only
                        out[b * SW + i] = v;
                    } else {                                          // outputs only
                        if (i >= SW - OUT_W) out[b * OUT_W + (i - (SW - OUT_W))] = v;
                    }
                }
            }
        }
        gbar(barcnt, qr, cg);
    }
}

// ---------------- launch ----------------
extern "C" void kernel_launch(void* const* d_in, const int* in_sizes, int n_in,
                              void* d_out, int out_size) {
    const float* x    = (const float*)d_in[0];
    const float* init = (const float*)d_in[1];
    const int*   rp   = (const int*)  d_in[2];
    const float* W1   = (const float*)d_in[3];
    const float* b1   = (const float*)d_in[4];
    const float* W2   = (const float*)d_in[5];
    const float* b2   = (const float*)d_in[6];

    setup_kernel<<<64, 256>>>(x, init, rp);

    const int smem_bytes = (2 * JS * PADC + QROWS * PADC) * (int)sizeof(__nv_bfloat16)
                         + 6 * 128 * (int)sizeof(float);
    cudaFuncSetAttribute(resrnn_kernel, cudaFuncAttributeMaxDynamicSharedMemorySize, smem_bytes);
    resrnn_kernel<<<P_CTAS, NTHREADS, smem_bytes>>>(x, rp, W1, b1, W2, b2,
                                                    (float*)d_out, out_size);
}